// round 1
// baseline (speedup 1.0000x reference)
#include <cuda_runtime.h>
#include <cstdint>
#include <math.h>

// Problem constants (fixed shapes)
#define DDIM   1024
#define NEXP   8
#define NTOK   8192           // B*T = 4*2048
#define NPAIR  (NTOK * 2)     // top-2 pairs

// GEMM tiling
#define BM 128
#define BN 128
#define BK 16

// -------- device scratch (static globals; no allocation) --------
__device__ float g_partial[(size_t)NPAIR * DDIM];  // 64 MB: per-pair expert output
__device__ int   g_list[NEXP * NPAIR];             // pair ids grouped by expert
__device__ int   g_count[NEXP];
__device__ int   g_expert[NPAIR];                  // expert id per pair
__device__ float g_weight[NPAIR];                  // softmax weight per pair

// -------- helpers --------
__device__ __forceinline__ float to_tf32(float x) {
    uint32_t u;
    asm("cvt.rna.tf32.f32 %0, %1;" : "=r"(u) : "f"(x));
    return __uint_as_float(u);
}

__device__ __forceinline__ void mma_tf32(float* c, const uint32_t* a, const uint32_t* b) {
    asm volatile(
        "mma.sync.aligned.m16n8k8.row.col.f32.tf32.tf32.f32 "
        "{%0,%1,%2,%3}, {%4,%5,%6,%7}, {%8,%9}, {%0,%1,%2,%3};\n"
        : "+f"(c[0]), "+f"(c[1]), "+f"(c[2]), "+f"(c[3])
        : "r"(a[0]), "r"(a[1]), "r"(a[2]), "r"(a[3]),
          "r"(b[0]), "r"(b[1]));
}

// -------- kernel 1: gating (one warp per token) --------
__global__ void gate_kernel(const float* __restrict__ x,
                            const float* __restrict__ gw,
                            const float* __restrict__ gb) {
    int warp = (blockIdx.x * blockDim.x + threadIdx.x) >> 5;
    int lane = threadIdx.x & 31;
    if (warp >= NTOK) return;
    const float* xr = x + (size_t)warp * DDIM;

    float acc[NEXP];
#pragma unroll
    for (int e = 0; e < NEXP; e++) acc[e] = 0.f;

    for (int i = lane; i < DDIM; i += 32) {
        float v = xr[i];
#pragma unroll
        for (int e = 0; e < NEXP; e++) acc[e] += v * gw[e * DDIM + i];
    }
#pragma unroll
    for (int e = 0; e < NEXP; e++) {
#pragma unroll
        for (int o = 16; o > 0; o >>= 1) acc[e] += __shfl_xor_sync(0xffffffffu, acc[e], o);
    }

    if (lane == 0) {
        float logits[NEXP];
#pragma unroll
        for (int e = 0; e < NEXP; e++) logits[e] = acc[e] + gb[e];
        // top-2, first occurrence on ties (matches jax.lax.top_k)
        int i0 = 0; float v0 = logits[0];
#pragma unroll
        for (int e = 1; e < NEXP; e++) if (logits[e] > v0) { v0 = logits[e]; i0 = e; }
        int i1 = -1; float v1 = -3.4e38f;
#pragma unroll
        for (int e = 0; e < NEXP; e++) if (e != i0 && logits[e] > v1) { v1 = logits[e]; i1 = e; }
        // softmax over the two logits (v0 >= v1)
        float e1 = expf(v1 - v0);
        float inv = 1.0f / (1.0f + e1);
        g_expert[warp * 2 + 0] = i0;
        g_expert[warp * 2 + 1] = i1;
        g_weight[warp * 2 + 0] = inv;
        g_weight[warp * 2 + 1] = e1 * inv;
    }
}

// -------- kernel 2: deterministic grouping (one warp per expert) --------
__global__ void group_kernel() {
    int w = threadIdx.x >> 5;      // expert id, 8 warps
    int lane = threadIdx.x & 31;
    int base = 0;
    for (int i = lane; i < NPAIR; i += 32) {
        int e = g_expert[i];
        unsigned m = __ballot_sync(0xffffffffu, e == w);
        if (e == w)
            g_list[w * NPAIR + base + __popc(m & ((1u << lane) - 1u))] = i;
        base += __popc(m);
    }
    if (lane == 0) g_count[w] = base;
}

// -------- kernel 3: grouped GEMM, tf32 mma.sync --------
// partial[pair, f] = sum_d delta[tok(pair), d] * W[e][f][d]
__global__ void gemm_kernel(const float* __restrict__ delta,
                            const float* __restrict__ W) {
    const int e   = blockIdx.z;
    const int cnt = g_count[e];
    const int m0  = blockIdx.y * BM;
    if (m0 >= cnt) return;
    const int n0  = blockIdx.x * BN;

    __shared__ int   s_pid[BM];
    __shared__ int   s_tok[BM];
    __shared__ float As[BM][BK + 1];
    __shared__ float Bs[BN][BK + 1];

    const int t = threadIdx.x;
    if (t < BM) {
        int p = (m0 + t < cnt) ? g_list[e * NPAIR + m0 + t] : -1;
        s_pid[t] = p;
        s_tok[t] = (p >= 0) ? (p >> 1) : 0;
    }
    __syncthreads();

    const float* Wb = W + (size_t)e * DDIM * DDIM;

    const int warpId = t >> 5;
    const int lane   = t & 31;
    const int warpM  = warpId & 3;   // 4 warps along M
    const int warpN  = warpId >> 2;  // 2 warps along N
    const int gid    = lane >> 2;    // 0..7
    const int qid    = lane & 3;     // 0..3

    float acc[2][8][4];
#pragma unroll
    for (int mt = 0; mt < 2; mt++)
#pragma unroll
        for (int nt = 0; nt < 8; nt++)
#pragma unroll
            for (int j = 0; j < 4; j++) acc[mt][nt][j] = 0.f;

    for (int kb = 0; kb < DDIM; kb += BK) {
        __syncthreads();  // protect smem from previous compute iteration
        // load A tile: 128 rows x 16 cols = 512 float4, 2 per thread
#pragma unroll
        for (int s = 0; s < 2; s++) {
            int i  = t + s * 256;
            int r  = i >> 2;
            int c4 = i & 3;
            const float4 v = *(const float4*)(delta + (size_t)s_tok[r] * DDIM + kb + c4 * 4);
            float* dst = &As[r][c4 * 4];
            dst[0] = to_tf32(v.x); dst[1] = to_tf32(v.y);
            dst[2] = to_tf32(v.z); dst[3] = to_tf32(v.w);
        }
        // load B tile: 128 n-rows x 16 k-cols
#pragma unroll
        for (int s = 0; s < 2; s++) {
            int i  = t + s * 256;
            int r  = i >> 2;
            int c4 = i & 3;
            const float4 v = *(const float4*)(Wb + (size_t)(n0 + r) * DDIM + kb + c4 * 4);
            float* dst = &Bs[r][c4 * 4];
            dst[0] = to_tf32(v.x); dst[1] = to_tf32(v.y);
            dst[2] = to_tf32(v.z); dst[3] = to_tf32(v.w);
        }
        __syncthreads();

#pragma unroll
        for (int ks = 0; ks < 2; ks++) {
            const int kk = ks * 8;
            uint32_t afr[2][4];
#pragma unroll
            for (int mt = 0; mt < 2; mt++) {
                int r = warpM * 32 + mt * 16 + gid;
                afr[mt][0] = __float_as_uint(As[r][kk + qid]);
                afr[mt][1] = __float_as_uint(As[r + 8][kk + qid]);
                afr[mt][2] = __float_as_uint(As[r][kk + qid + 4]);
                afr[mt][3] = __float_as_uint(As[r + 8][kk + qid + 4]);
            }
            uint32_t bfr[8][2];
#pragma unroll
            for (int nt = 0; nt < 8; nt++) {
                int n = warpN * 64 + nt * 8 + gid;
                bfr[nt][0] = __float_as_uint(Bs[n][kk + qid]);
                bfr[nt][1] = __float_as_uint(Bs[n][kk + qid + 4]);
            }
#pragma unroll
            for (int mt = 0; mt < 2; mt++)
#pragma unroll
                for (int nt = 0; nt < 8; nt++)
                    mma_tf32(acc[mt][nt], afr[mt], bfr[nt]);
        }
    }

    // epilogue: write partial rows (guard invalid rows)
#pragma unroll
    for (int mt = 0; mt < 2; mt++) {
        int rl0 = warpM * 32 + mt * 16 + gid;
        int rl1 = rl0 + 8;
        int p0 = s_pid[rl0];
        int p1 = s_pid[rl1];
#pragma unroll
        for (int nt = 0; nt < 8; nt++) {
            int c = n0 + warpN * 64 + nt * 8 + qid * 2;
            if (p0 >= 0)
                *(float2*)(g_partial + (size_t)p0 * DDIM + c) =
                    make_float2(acc[mt][nt][0], acc[mt][nt][1]);
            if (p1 >= 0)
                *(float2*)(g_partial + (size_t)p1 * DDIM + c) =
                    make_float2(acc[mt][nt][2], acc[mt][nt][3]);
        }
    }
}

// -------- kernel 4: weighted combine with expert bias --------
__global__ void combine_kernel(const float* __restrict__ eb, float* __restrict__ out) {
    int i   = blockIdx.x * blockDim.x + threadIdx.x;  // over NTOK * (DDIM/4)
    int tok = i >> 8;          // DDIM/4 = 256
    int c4  = i & 255;
    float w0 = g_weight[tok * 2 + 0], w1 = g_weight[tok * 2 + 1];
    int   e0 = g_expert[tok * 2 + 0], e1 = g_expert[tok * 2 + 1];

    float4 p0 = ((const float4*)(g_partial + (size_t)(tok * 2 + 0) * DDIM))[c4];
    float4 p1 = ((const float4*)(g_partial + (size_t)(tok * 2 + 1) * DDIM))[c4];
    float4 b0 = ((const float4*)(eb + (size_t)e0 * DDIM))[c4];
    float4 b1 = ((const float4*)(eb + (size_t)e1 * DDIM))[c4];

    float4 r;
    r.x = w0 * (p0.x + b0.x) + w1 * (p1.x + b1.x);
    r.y = w0 * (p0.y + b0.y) + w1 * (p1.y + b1.y);
    r.z = w0 * (p0.z + b0.z) + w1 * (p1.z + b1.z);
    r.w = w0 * (p0.w + b0.w) + w1 * (p1.w + b1.w);
    ((float4*)out)[i] = r;
}

// -------- launch --------
extern "C" void kernel_launch(void* const* d_in, const int* in_sizes, int n_in,
                              void* d_out, int out_size) {
    const float* input_feat = (const float*)d_in[0];  // [B,T,D]
    const float* delta      = (const float*)d_in[1];  // [B,T,D]
    const float* gate_W     = (const float*)d_in[2];  // [E,D]
    const float* gate_b     = (const float*)d_in[3];  // [E]
    const float* expert_W   = (const float*)d_in[4];  // [E,D,D]
    const float* expert_b   = (const float*)d_in[5];  // [E,D]
    float* out = (float*)d_out;

    gate_kernel<<<NTOK / 8, 256>>>(input_feat, gate_W, gate_b);
    group_kernel<<<1, 256>>>();
    dim3 grid(DDIM / BN, NPAIR / BM, NEXP);
    gemm_kernel<<<grid, 256>>>(delta, expert_W);
    combine_kernel<<<(NTOK * (DDIM / 4)) / 256, 256>>>(expert_b, out);
}

// round 3
// speedup vs baseline: 1.2034x; 1.2034x over previous
#include <cuda_runtime.h>
#include <cstdint>
#include <math.h>

// Problem constants
#define DDIM   1024
#define NEXP   8
#define NTOK   8192
#define NPAIR  (NTOK * 2)

// GEMM tiling
#define BM 128
#define BN 128
#define BK 32
#define STAGES 3
#define A_BYTES (BM * BK * 4)              // 16384
#define B_BYTES (BN * BK * 4)              // 16384
#define STAGE_BYTES (A_BYTES + B_BYTES)    // 32768
#define SMEM_BYTES (STAGES * STAGE_BYTES)  // 98304

// -------- device scratch (static globals; no allocation) --------
__device__ float g_partial[(size_t)NPAIR * DDIM];   // 64 MB
__device__ float g_rdelta[(size_t)NTOK * DDIM];     // 32 MB tf32-rounded delta
__device__ float g_rW[(size_t)NEXP * DDIM * DDIM];  // 32 MB tf32-rounded expert_W
__device__ int   g_list[NEXP * NPAIR];
__device__ int   g_count[NEXP];
__device__ int   g_expert[NPAIR];
__device__ float g_weight[NPAIR];

// -------- helpers --------
__device__ __forceinline__ float to_tf32(float x) {
    uint32_t u;
    asm("cvt.rna.tf32.f32 %0, %1;" : "=r"(u) : "f"(x));
    return __uint_as_float(u);
}
__device__ __forceinline__ uint32_t smem_u32(const void* p) {
    uint32_t a;
    asm("{ .reg .u64 t; cvta.to.shared.u64 t, %1; cvt.u32.u64 %0, t; }" : "=r"(a) : "l"(p));
    return a;
}
__device__ __forceinline__ void cp_async16(uint32_t saddr, const void* gaddr) {
    asm volatile("cp.async.cg.shared.global [%0], [%1], 16;\n" :: "r"(saddr), "l"(gaddr));
}
__device__ __forceinline__ void cp_commit() { asm volatile("cp.async.commit_group;\n" ::: "memory"); }
template <int N>
__device__ __forceinline__ void cp_wait() { asm volatile("cp.async.wait_group %0;\n" :: "n"(N) : "memory"); }

__device__ __forceinline__ void mma_tf32(float* c, const uint32_t* a, const uint32_t* b) {
    asm volatile(
        "mma.sync.aligned.m16n8k8.row.col.f32.tf32.tf32.f32 "
        "{%0,%1,%2,%3}, {%4,%5,%6,%7}, {%8,%9}, {%0,%1,%2,%3};\n"
        : "+f"(c[0]), "+f"(c[1]), "+f"(c[2]), "+f"(c[3])
        : "r"(a[0]), "r"(a[1]), "r"(a[2]), "r"(a[3]),
          "r"(b[0]), "r"(b[1]));
}

// -------- kernel 0: tf32 pre-round --------
__global__ void round_kernel(const float* __restrict__ src, float* __restrict__ dst, int n4) {
    int i = blockIdx.x * blockDim.x + threadIdx.x;
    if (i >= n4) return;
    float4 v = ((const float4*)src)[i];
    v.x = to_tf32(v.x); v.y = to_tf32(v.y); v.z = to_tf32(v.z); v.w = to_tf32(v.w);
    ((float4*)dst)[i] = v;
}

// -------- kernel 1: gating (one warp per token) --------
__global__ void gate_kernel(const float* __restrict__ x,
                            const float* __restrict__ gw,
                            const float* __restrict__ gb) {
    int warp = (blockIdx.x * blockDim.x + threadIdx.x) >> 5;
    int lane = threadIdx.x & 31;
    if (warp >= NTOK) return;
    const float* xr = x + (size_t)warp * DDIM;

    float acc[NEXP];
#pragma unroll
    for (int e = 0; e < NEXP; e++) acc[e] = 0.f;
    for (int i = lane; i < DDIM; i += 32) {
        float v = xr[i];
#pragma unroll
        for (int e = 0; e < NEXP; e++) acc[e] += v * gw[e * DDIM + i];
    }
#pragma unroll
    for (int e = 0; e < NEXP; e++) {
#pragma unroll
        for (int o = 16; o > 0; o >>= 1) acc[e] += __shfl_xor_sync(0xffffffffu, acc[e], o);
    }
    if (lane == 0) {
        float logits[NEXP];
#pragma unroll
        for (int e = 0; e < NEXP; e++) logits[e] = acc[e] + gb[e];
        int i0 = 0; float v0 = logits[0];
#pragma unroll
        for (int e = 1; e < NEXP; e++) if (logits[e] > v0) { v0 = logits[e]; i0 = e; }
        int i1 = -1; float v1 = -3.4e38f;
#pragma unroll
        for (int e = 0; e < NEXP; e++) if (e != i0 && logits[e] > v1) { v1 = logits[e]; i1 = e; }
        float e1 = expf(v1 - v0);
        float inv = 1.0f / (1.0f + e1);
        g_expert[warp * 2 + 0] = i0;
        g_expert[warp * 2 + 1] = i1;
        g_weight[warp * 2 + 0] = inv;
        g_weight[warp * 2 + 1] = e1 * inv;
    }
}

// -------- kernel 2: deterministic grouping (one warp per expert) --------
__global__ void group_kernel() {
    int w = threadIdx.x >> 5;
    int lane = threadIdx.x & 31;
    int base = 0;
    for (int i = lane; i < NPAIR; i += 32) {
        int e = g_expert[i];
        unsigned m = __ballot_sync(0xffffffffu, e == w);
        if (e == w)
            g_list[w * NPAIR + base + __popc(m & ((1u << lane) - 1u))] = i;
        base += __popc(m);
    }
    if (lane == 0) g_count[w] = base;
}

// -------- kernel 3: grouped GEMM, tf32 mma.sync, 3-stage cp.async pipeline --------
// smem per stage: A [4 k8-groups][128 rows][8 floats], then B same for 128 n-rows.
__global__ void __launch_bounds__(256, 2) gemm_kernel() {
    const int e   = blockIdx.z;
    const int cnt = g_count[e];
    const int m0  = blockIdx.y * BM;
    if (m0 >= cnt) return;
    const int n0  = blockIdx.x * BN;

    extern __shared__ char smem[];
    __shared__ int s_pid[BM];
    __shared__ int s_tok[BM];

    const uint32_t smem_base = smem_u32(smem);
    const int tid = threadIdx.x;
    const int wid = tid >> 5;
    const int lane = tid & 31;
    const int warpM = wid & 1;    // 2 bands of 64 rows
    const int warpN = wid >> 1;   // 4 bands of 32 cols
    const int gid = lane >> 2;    // 0..7
    const int qid = lane & 3;     // 0..3

    if (tid < BM) {
        int p = (m0 + tid < cnt) ? g_list[e * NPAIR + m0 + tid] : -1;
        s_pid[tid] = p;
        s_tok[tid] = (p >= 0) ? (p >> 1) : 0;
    }
    __syncthreads();

    const float* __restrict__ Wb = g_rW + (size_t)e * DDIM * DDIM;
    const int NKB = DDIM / BK;  // 32

    auto issue_loads = [&](int kb) {
        const uint32_t sbase = smem_base + (uint32_t)(kb % STAGES) * STAGE_BYTES;
        const int kbase = kb * BK;
        // A: 1024 16B-chunks, 4 per thread
#pragma unroll
        for (int i = 0; i < 4; i++) {
            int idx = tid + i * 256;
            int r = idx >> 3, c4 = idx & 7;
            const float* g = g_rdelta + (size_t)s_tok[r] * DDIM + kbase + c4 * 4;
            uint32_t sa = sbase + ((uint32_t)(c4 >> 1) << 12) + r * 32 + ((c4 & 1) << 4);
            cp_async16(sa, g);
        }
        // B: 1024 16B-chunks, 4 per thread
#pragma unroll
        for (int i = 0; i < 4; i++) {
            int idx = tid + i * 256;
            int r = idx >> 3, c4 = idx & 7;
            const float* g = Wb + (size_t)(n0 + r) * DDIM + kbase + c4 * 4;
            uint32_t sa = sbase + A_BYTES + ((uint32_t)(c4 >> 1) << 12) + r * 32 + ((c4 & 1) << 4);
            cp_async16(sa, g);
        }
        cp_commit();
    };

    float acc[4][4][4];
#pragma unroll
    for (int mt = 0; mt < 4; mt++)
#pragma unroll
        for (int nt = 0; nt < 4; nt++)
#pragma unroll
            for (int j = 0; j < 4; j++) acc[mt][nt][j] = 0.f;

    issue_loads(0);
    issue_loads(1);

    for (int kb = 0; kb < NKB; kb++) {
        if (kb + 2 < NKB) cp_wait<1>(); else cp_wait<0>();
        __syncthreads();
        if (kb + 2 < NKB) issue_loads(kb + 2);

        const float* As = (const float*)(smem + (kb % STAGES) * STAGE_BYTES);
        const float* Bs = As + BM * BK;  // 4096 floats

#pragma unroll
        for (int ks = 0; ks < 4; ks++) {
            const int ko = ks * 1024;
            uint32_t a[4][4];
#pragma unroll
            for (int mt = 0; mt < 4; mt++) {
                int r = warpM * 64 + mt * 16 + gid;
                a[mt][0] = __float_as_uint(As[ko + r * 8 + qid]);
                a[mt][1] = __float_as_uint(As[ko + (r + 8) * 8 + qid]);
                a[mt][2] = __float_as_uint(As[ko + r * 8 + qid + 4]);
                a[mt][3] = __float_as_uint(As[ko + (r + 8) * 8 + qid + 4]);
            }
            uint32_t b[4][2];
#pragma unroll
            for (int nt = 0; nt < 4; nt++) {
                int n = warpN * 32 + nt * 8 + gid;
                b[nt][0] = __float_as_uint(Bs[ko + n * 8 + qid]);
                b[nt][1] = __float_as_uint(Bs[ko + n * 8 + qid + 4]);
            }
#pragma unroll
            for (int mt = 0; mt < 4; mt++)
#pragma unroll
                for (int nt = 0; nt < 4; nt++)
                    mma_tf32(acc[mt][nt], a[mt], b[nt]);
        }
        __syncthreads();
    }

    // epilogue: float2 stores to g_partial
#pragma unroll
    for (int mt = 0; mt < 4; mt++) {
        int r0 = warpM * 64 + mt * 16 + gid;
        int r1 = r0 + 8;
        int p0 = s_pid[r0];
        int p1 = s_pid[r1];
#pragma unroll
        for (int nt = 0; nt < 4; nt++) {
            int c = n0 + warpN * 32 + nt * 8 + qid * 2;
            if (p0 >= 0)
                *(float2*)(g_partial + (size_t)p0 * DDIM + c) =
                    make_float2(acc[mt][nt][0], acc[mt][nt][1]);
            if (p1 >= 0)
                *(float2*)(g_partial + (size_t)p1 * DDIM + c) =
                    make_float2(acc[mt][nt][2], acc[mt][nt][3]);
        }
    }
}

// -------- kernel 4: weighted combine with expert bias --------
__global__ void combine_kernel(const float* __restrict__ eb, float* __restrict__ out) {
    int i   = blockIdx.x * blockDim.x + threadIdx.x;
    int tok = i >> 8;
    int c4  = i & 255;
    float w0 = g_weight[tok * 2 + 0], w1 = g_weight[tok * 2 + 1];
    int   e0 = g_expert[tok * 2 + 0], e1 = g_expert[tok * 2 + 1];

    float4 p0 = ((const float4*)(g_partial + (size_t)(tok * 2 + 0) * DDIM))[c4];
    float4 p1 = ((const float4*)(g_partial + (size_t)(tok * 2 + 1) * DDIM))[c4];
    float4 b0 = ((const float4*)(eb + (size_t)e0 * DDIM))[c4];
    float4 b1 = ((const float4*)(eb + (size_t)e1 * DDIM))[c4];

    float4 r;
    r.x = w0 * (p0.x + b0.x) + w1 * (p1.x + b1.x);
    r.y = w0 * (p0.y + b0.y) + w1 * (p1.y + b1.y);
    r.z = w0 * (p0.z + b0.z) + w1 * (p1.z + b1.z);
    r.w = w0 * (p0.w + b0.w) + w1 * (p1.w + b1.w);
    ((float4*)out)[i] = r;
}

// -------- launch --------
extern "C" void kernel_launch(void* const* d_in, const int* in_sizes, int n_in,
                              void* d_out, int out_size) {
    const float* input_feat = (const float*)d_in[0];
    const float* delta      = (const float*)d_in[1];
    const float* gate_W     = (const float*)d_in[2];
    const float* gate_b     = (const float*)d_in[3];
    const float* expert_W   = (const float*)d_in[4];
    const float* expert_b   = (const float*)d_in[5];
    float* out = (float*)d_out;

    cudaFuncSetAttribute(gemm_kernel, cudaFuncAttributeMaxDynamicSharedMemorySize, SMEM_BYTES);

    float* rdelta; cudaGetSymbolAddress((void**)&rdelta, g_rdelta);
    float* rW;     cudaGetSymbolAddress((void**)&rW, g_rW);

    round_kernel<<<(NTOK * DDIM / 4) / 256, 256>>>(delta, rdelta, NTOK * DDIM / 4);
    round_kernel<<<(NEXP * DDIM * DDIM / 4) / 256, 256>>>(expert_W, rW, NEXP * DDIM * DDIM / 4);
    gate_kernel<<<NTOK / 8, 256>>>(input_feat, gate_W, gate_b);
    group_kernel<<<1, 256>>>();
    dim3 grid(DDIM / BN, NPAIR / BM, NEXP);
    gemm_kernel<<<grid, 256, SMEM_BYTES>>>();
    combine_kernel<<<(NTOK * (DDIM / 4)) / 256, 256>>>(expert_b, out);
}

// round 4
// speedup vs baseline: 1.5485x; 1.2868x over previous
#include <cuda_runtime.h>
#include <cstdint>
#include <math.h>

// Problem constants
#define DDIM   1024
#define NEXP   8
#define NTOK   8192
#define NPAIR  (NTOK * 2)

// GEMM tiling
#define BM 128
#define BN 128
#define BK 32
#define STAGES 3
#define A_BYTES (BM * BK * 4)              // 16384
#define B_BYTES (BN * BK * 4)              // 16384
#define STAGE_BYTES (A_BYTES + B_BYTES)    // 32768
#define SMEM_BYTES (STAGES * STAGE_BYTES)  // 98304

// -------- device scratch (static globals; no allocation) --------
__device__ float g_partial[(size_t)NPAIR * DDIM];   // 64 MB
__device__ float g_rdelta[(size_t)NTOK * DDIM];     // 32 MB tf32-rounded delta
__device__ float g_rW[(size_t)NEXP * DDIM * DDIM];  // 32 MB tf32-rounded expert_W
__device__ int   g_list[NEXP * NPAIR];
__device__ int   g_count[NEXP];
__device__ int   g_expert[NPAIR];
__device__ float g_weight[NPAIR];

// -------- helpers --------
__device__ __forceinline__ float to_tf32(float x) {
    uint32_t u;
    asm("cvt.rna.tf32.f32 %0, %1;" : "=r"(u) : "f"(x));
    return __uint_as_float(u);
}
__device__ __forceinline__ uint32_t smem_u32(const void* p) {
    uint32_t a;
    asm("{ .reg .u64 t; cvta.to.shared.u64 t, %1; cvt.u32.u64 %0, t; }" : "=r"(a) : "l"(p));
    return a;
}
__device__ __forceinline__ void cp_async16(uint32_t saddr, const void* gaddr) {
    asm volatile("cp.async.cg.shared.global [%0], [%1], 16;\n" :: "r"(saddr), "l"(gaddr));
}
__device__ __forceinline__ void cp_commit() { asm volatile("cp.async.commit_group;\n" ::: "memory"); }
template <int N>
__device__ __forceinline__ void cp_wait() { asm volatile("cp.async.wait_group %0;\n" :: "n"(N) : "memory"); }

__device__ __forceinline__ void mma_tf32(float* c, const uint32_t* a, const uint32_t* b) {
    asm volatile(
        "mma.sync.aligned.m16n8k8.row.col.f32.tf32.tf32.f32 "
        "{%0,%1,%2,%3}, {%4,%5,%6,%7}, {%8,%9}, {%0,%1,%2,%3};\n"
        : "+f"(c[0]), "+f"(c[1]), "+f"(c[2]), "+f"(c[3])
        : "r"(a[0]), "r"(a[1]), "r"(a[2]), "r"(a[3]),
          "r"(b[0]), "r"(b[1]));
}

// -------- kernel 0: tf32 pre-round --------
__global__ void round_kernel(const float* __restrict__ src, float* __restrict__ dst, int n4) {
    int i = blockIdx.x * blockDim.x + threadIdx.x;
    if (i >= n4) return;
    float4 v = ((const float4*)src)[i];
    v.x = to_tf32(v.x); v.y = to_tf32(v.y); v.z = to_tf32(v.z); v.w = to_tf32(v.w);
    ((float4*)dst)[i] = v;
}

// -------- kernel 1: gating (one warp per token) --------
__global__ void gate_kernel(const float* __restrict__ x,
                            const float* __restrict__ gw,
                            const float* __restrict__ gb) {
    int warp = (blockIdx.x * blockDim.x + threadIdx.x) >> 5;
    int lane = threadIdx.x & 31;
    if (warp >= NTOK) return;
    const float* xr = x + (size_t)warp * DDIM;

    float acc[NEXP];
#pragma unroll
    for (int e = 0; e < NEXP; e++) acc[e] = 0.f;
    for (int i = lane; i < DDIM; i += 32) {
        float v = xr[i];
#pragma unroll
        for (int e = 0; e < NEXP; e++) acc[e] += v * gw[e * DDIM + i];
    }
#pragma unroll
    for (int e = 0; e < NEXP; e++) {
#pragma unroll
        for (int o = 16; o > 0; o >>= 1) acc[e] += __shfl_xor_sync(0xffffffffu, acc[e], o);
    }
    if (lane == 0) {
        float logits[NEXP];
#pragma unroll
        for (int e = 0; e < NEXP; e++) logits[e] = acc[e] + gb[e];
        int i0 = 0; float v0 = logits[0];
#pragma unroll
        for (int e = 1; e < NEXP; e++) if (logits[e] > v0) { v0 = logits[e]; i0 = e; }
        int i1 = -1; float v1 = -3.4e38f;
#pragma unroll
        for (int e = 0; e < NEXP; e++) if (e != i0 && logits[e] > v1) { v1 = logits[e]; i1 = e; }
        float e1 = expf(v1 - v0);
        float inv = 1.0f / (1.0f + e1);
        g_expert[warp * 2 + 0] = i0;
        g_expert[warp * 2 + 1] = i1;
        g_weight[warp * 2 + 0] = inv;
        g_weight[warp * 2 + 1] = e1 * inv;
    }
}

// -------- kernel 2: deterministic grouping via count+scan+scatter --------
// One block, 1024 threads. Thread t owns contiguous pairs [t*16, t*16+16).
// Per-expert order = ascending pair id (same as sequential compaction).
#define GT   1024
#define GPER (NPAIR / GT)   // 16
__global__ void __launch_bounds__(GT) group_kernel() {
    __shared__ uint16_t s_hist[NEXP][GT];   // 16 KB
    const int t = threadIdx.x;

    uint8_t ex[GPER];
    uint16_t cnt[NEXP];
#pragma unroll
    for (int e = 0; e < NEXP; e++) cnt[e] = 0;
#pragma unroll
    for (int i = 0; i < GPER; i++) {
        int e = g_expert[t * GPER + i];
        ex[i] = (uint8_t)e;
        cnt[e]++;
    }
#pragma unroll
    for (int e = 0; e < NEXP; e++) s_hist[e][t] = cnt[e];
    __syncthreads();

    // inclusive scan over threads, per expert (Hillis-Steele)
#pragma unroll
    for (int off = 1; off < GT; off <<= 1) {
        uint16_t v[NEXP];
#pragma unroll
        for (int e = 0; e < NEXP; e++) v[e] = (t >= off) ? s_hist[e][t - off] : (uint16_t)0;
        __syncthreads();
#pragma unroll
        for (int e = 0; e < NEXP; e++) s_hist[e][t] = s_hist[e][t] + v[e];
        __syncthreads();
    }

    int off[NEXP];
#pragma unroll
    for (int e = 0; e < NEXP; e++) off[e] = (int)s_hist[e][t] - (int)cnt[e];  // exclusive
#pragma unroll
    for (int i = 0; i < GPER; i++) {
        int e = ex[i];
        g_list[e * NPAIR + off[e]] = t * GPER + i;
        off[e]++;
    }
    if (t == GT - 1) {
#pragma unroll
        for (int e = 0; e < NEXP; e++) g_count[e] = (int)s_hist[e][GT - 1];
    }
}

// -------- kernel 3: grouped GEMM, tf32 mma.sync, 3-stage cp.async pipeline --------
__global__ void __launch_bounds__(256, 2) gemm_kernel() {
    const int e   = blockIdx.z;
    const int cnt = g_count[e];
    const int m0  = blockIdx.y * BM;
    if (m0 >= cnt) return;
    const int n0  = blockIdx.x * BN;

    extern __shared__ char smem[];
    __shared__ int s_pid[BM];
    __shared__ int s_tok[BM];

    const uint32_t smem_base = smem_u32(smem);
    const int tid = threadIdx.x;
    const int wid = tid >> 5;
    const int lane = tid & 31;
    const int warpM = wid & 1;
    const int warpN = wid >> 1;
    const int gid = lane >> 2;
    const int qid = lane & 3;

    if (tid < BM) {
        int p = (m0 + tid < cnt) ? g_list[e * NPAIR + m0 + tid] : -1;
        s_pid[tid] = p;
        s_tok[tid] = (p >= 0) ? (p >> 1) : 0;
    }
    __syncthreads();

    const float* __restrict__ Wb = g_rW + (size_t)e * DDIM * DDIM;
    const int NKB = DDIM / BK;  // 32

    auto issue_loads = [&](int kb) {
        const uint32_t sbase = smem_base + (uint32_t)(kb % STAGES) * STAGE_BYTES;
        const int kbase = kb * BK;
#pragma unroll
        for (int i = 0; i < 4; i++) {
            int idx = tid + i * 256;
            int r = idx >> 3, c4 = idx & 7;
            const float* g = g_rdelta + (size_t)s_tok[r] * DDIM + kbase + c4 * 4;
            uint32_t sa = sbase + ((uint32_t)(c4 >> 1) << 12) + r * 32 + ((c4 & 1) << 4);
            cp_async16(sa, g);
        }
#pragma unroll
        for (int i = 0; i < 4; i++) {
            int idx = tid + i * 256;
            int r = idx >> 3, c4 = idx & 7;
            const float* g = Wb + (size_t)(n0 + r) * DDIM + kbase + c4 * 4;
            uint32_t sa = sbase + A_BYTES + ((uint32_t)(c4 >> 1) << 12) + r * 32 + ((c4 & 1) << 4);
            cp_async16(sa, g);
        }
        cp_commit();
    };

    float acc[4][4][4];
#pragma unroll
    for (int mt = 0; mt < 4; mt++)
#pragma unroll
        for (int nt = 0; nt < 4; nt++)
#pragma unroll
            for (int j = 0; j < 4; j++) acc[mt][nt][j] = 0.f;

    issue_loads(0);
    issue_loads(1);

    for (int kb = 0; kb < NKB; kb++) {
        if (kb + 2 < NKB) cp_wait<1>(); else cp_wait<0>();
        __syncthreads();
        if (kb + 2 < NKB) issue_loads(kb + 2);

        const float* As = (const float*)(smem + (kb % STAGES) * STAGE_BYTES);
        const float* Bs = As + BM * BK;

#pragma unroll
        for (int ks = 0; ks < 4; ks++) {
            const int ko = ks * 1024;
            uint32_t a[4][4];
#pragma unroll
            for (int mt = 0; mt < 4; mt++) {
                int r = warpM * 64 + mt * 16 + gid;
                a[mt][0] = __float_as_uint(As[ko + r * 8 + qid]);
                a[mt][1] = __float_as_uint(As[ko + (r + 8) * 8 + qid]);
                a[mt][2] = __float_as_uint(As[ko + r * 8 + qid + 4]);
                a[mt][3] = __float_as_uint(As[ko + (r + 8) * 8 + qid + 4]);
            }
            uint32_t b[4][2];
#pragma unroll
            for (int nt = 0; nt < 4; nt++) {
                int n = warpN * 32 + nt * 8 + gid;
                b[nt][0] = __float_as_uint(Bs[ko + n * 8 + qid]);
                b[nt][1] = __float_as_uint(Bs[ko + n * 8 + qid + 4]);
            }
#pragma unroll
            for (int mt = 0; mt < 4; mt++)
#pragma unroll
                for (int nt = 0; nt < 4; nt++)
                    mma_tf32(acc[mt][nt], a[mt], b[nt]);
        }
        __syncthreads();
    }

#pragma unroll
    for (int mt = 0; mt < 4; mt++) {
        int r0 = warpM * 64 + mt * 16 + gid;
        int r1 = r0 + 8;
        int p0 = s_pid[r0];
        int p1 = s_pid[r1];
#pragma unroll
        for (int nt = 0; nt < 4; nt++) {
            int c = n0 + warpN * 32 + nt * 8 + qid * 2;
            if (p0 >= 0)
                *(float2*)(g_partial + (size_t)p0 * DDIM + c) =
                    make_float2(acc[mt][nt][0], acc[mt][nt][1]);
            if (p1 >= 0)
                *(float2*)(g_partial + (size_t)p1 * DDIM + c) =
                    make_float2(acc[mt][nt][2], acc[mt][nt][3]);
        }
    }
}

// -------- kernel 4: weighted combine with expert bias --------
__global__ void combine_kernel(const float* __restrict__ eb, float* __restrict__ out) {
    int i   = blockIdx.x * blockDim.x + threadIdx.x;
    int tok = i >> 8;
    int c4  = i & 255;
    float w0 = g_weight[tok * 2 + 0], w1 = g_weight[tok * 2 + 1];
    int   e0 = g_expert[tok * 2 + 0], e1 = g_expert[tok * 2 + 1];

    float4 p0 = ((const float4*)(g_partial + (size_t)(tok * 2 + 0) * DDIM))[c4];
    float4 p1 = ((const float4*)(g_partial + (size_t)(tok * 2 + 1) * DDIM))[c4];
    float4 b0 = ((const float4*)(eb + (size_t)e0 * DDIM))[c4];
    float4 b1 = ((const float4*)(eb + (size_t)e1 * DDIM))[c4];

    float4 r;
    r.x = w0 * (p0.x + b0.x) + w1 * (p1.x + b1.x);
    r.y = w0 * (p0.y + b0.y) + w1 * (p1.y + b1.y);
    r.z = w0 * (p0.z + b0.z) + w1 * (p1.z + b1.z);
    r.w = w0 * (p0.w + b0.w) + w1 * (p1.w + b1.w);
    ((float4*)out)[i] = r;
}

// -------- launch --------
extern "C" void kernel_launch(void* const* d_in, const int* in_sizes, int n_in,
                              void* d_out, int out_size) {
    const float* input_feat = (const float*)d_in[0];
    const float* delta      = (const float*)d_in[1];
    const float* gate_W     = (const float*)d_in[2];
    const float* gate_b     = (const float*)d_in[3];
    const float* expert_W   = (const float*)d_in[4];
    const float* expert_b   = (const float*)d_in[5];
    float* out = (float*)d_out;

    cudaFuncSetAttribute(gemm_kernel, cudaFuncAttributeMaxDynamicSharedMemorySize, SMEM_BYTES);

    float* rdelta; cudaGetSymbolAddress((void**)&rdelta, g_rdelta);
    float* rW;     cudaGetSymbolAddress((void**)&rW, g_rW);

    round_kernel<<<(NTOK * DDIM / 4) / 256, 256>>>(delta, rdelta, NTOK * DDIM / 4);
    round_kernel<<<(NEXP * DDIM * DDIM / 4) / 256, 256>>>(expert_W, rW, NEXP * DDIM * DDIM / 4);
    gate_kernel<<<NTOK / 8, 256>>>(input_feat, gate_W, gate_b);
    group_kernel<<<1, GT>>>();
    dim3 grid(DDIM / BN, NPAIR / BM, NEXP);
    gemm_kernel<<<grid, 256, SMEM_BYTES>>>();
    combine_kernel<<<(NTOK * (DDIM / 4)) / 256, 256>>>(expert_b, out);
}

// round 5
// speedup vs baseline: 2.0541x; 1.3265x over previous
#include <cuda_runtime.h>
#include <cstdint>
#include <math.h>

// Problem constants
#define DDIM   1024
#define NEXP   8
#define NTOK   8192
#define NPAIR  (NTOK * 2)

// GEMM tiling: CTA 128x256, 8 warps of 64x64, BK=32, 3-stage cp.async
#define BM 128
#define BN 256
#define BK 32
#define STAGES 3
#define A_BYTES (BM * BK * 4)              // 16384
#define B_BYTES (BN * BK * 4)              // 32768
#define STAGE_BYTES (A_BYTES + B_BYTES)    // 49152
#define SMEM_BYTES (STAGES * STAGE_BYTES)  // 147456

// -------- device scratch --------
__device__ float g_partial[(size_t)NPAIR * DDIM];   // 64 MB
__device__ float g_rdelta[(size_t)NTOK * DDIM];     // 32 MB tf32-rounded delta
__device__ float g_rW[(size_t)NEXP * DDIM * DDIM];  // 32 MB tf32-rounded expert_W
__device__ int   g_list[NEXP * NPAIR];
__device__ int   g_count[NEXP];
__device__ int   g_expert[NPAIR];
__device__ float g_weight[NPAIR];

// -------- helpers --------
__device__ __forceinline__ float to_tf32(float x) {
    uint32_t u;
    asm("cvt.rna.tf32.f32 %0, %1;" : "=r"(u) : "f"(x));
    return __uint_as_float(u);
}
__device__ __forceinline__ uint32_t smem_u32(const void* p) {
    uint32_t a;
    asm("{ .reg .u64 t; cvta.to.shared.u64 t, %1; cvt.u32.u64 %0, t; }" : "=r"(a) : "l"(p));
    return a;
}
__device__ __forceinline__ uint32_t swz128(uint32_t off) { return off ^ ((off >> 3) & 0x70u); }

__device__ __forceinline__ void cp_async16(uint32_t saddr, const void* gaddr) {
    asm volatile("cp.async.cg.shared.global [%0], [%1], 16;\n" :: "r"(saddr), "l"(gaddr));
}
__device__ __forceinline__ void cp_commit() { asm volatile("cp.async.commit_group;\n" ::: "memory"); }
template <int N>
__device__ __forceinline__ void cp_wait() { asm volatile("cp.async.wait_group %0;\n" :: "n"(N) : "memory"); }

__device__ __forceinline__ float lds32(uint32_t a) {
    float v;
    asm volatile("ld.shared.f32 %0, [%1];" : "=f"(v) : "r"(a));
    return v;
}

__device__ __forceinline__ void mma_tf32(float* c, const float* a, const float* b) {
    asm volatile(
        "mma.sync.aligned.m16n8k8.row.col.f32.tf32.tf32.f32 "
        "{%0,%1,%2,%3}, {%4,%5,%6,%7}, {%8,%9}, {%0,%1,%2,%3};\n"
        : "+f"(c[0]), "+f"(c[1]), "+f"(c[2]), "+f"(c[3])
        : "r"(__float_as_uint(a[0])), "r"(__float_as_uint(a[1])),
          "r"(__float_as_uint(a[2])), "r"(__float_as_uint(a[3])),
          "r"(__float_as_uint(b[0])), "r"(__float_as_uint(b[1])));
}

// -------- kernel 0: tf32 pre-round --------
__global__ void round_kernel(const float* __restrict__ src, float* __restrict__ dst, int n4) {
    int i = blockIdx.x * blockDim.x + threadIdx.x;
    if (i >= n4) return;
    float4 v = ((const float4*)src)[i];
    v.x = to_tf32(v.x); v.y = to_tf32(v.y); v.z = to_tf32(v.z); v.w = to_tf32(v.w);
    ((float4*)dst)[i] = v;
}

// -------- kernel 1: gating (one warp per token) --------
__global__ void gate_kernel(const float* __restrict__ x,
                            const float* __restrict__ gw,
                            const float* __restrict__ gb) {
    int warp = (blockIdx.x * blockDim.x + threadIdx.x) >> 5;
    int lane = threadIdx.x & 31;
    if (warp >= NTOK) return;
    const float* xr = x + (size_t)warp * DDIM;

    float acc[NEXP];
#pragma unroll
    for (int e = 0; e < NEXP; e++) acc[e] = 0.f;
    for (int i = lane; i < DDIM; i += 32) {
        float v = xr[i];
#pragma unroll
        for (int e = 0; e < NEXP; e++) acc[e] += v * gw[e * DDIM + i];
    }
#pragma unroll
    for (int e = 0; e < NEXP; e++) {
#pragma unroll
        for (int o = 16; o > 0; o >>= 1) acc[e] += __shfl_xor_sync(0xffffffffu, acc[e], o);
    }
    if (lane == 0) {
        float logits[NEXP];
#pragma unroll
        for (int e = 0; e < NEXP; e++) logits[e] = acc[e] + gb[e];
        int i0 = 0; float v0 = logits[0];
#pragma unroll
        for (int e = 1; e < NEXP; e++) if (logits[e] > v0) { v0 = logits[e]; i0 = e; }
        int i1 = -1; float v1 = -3.4e38f;
#pragma unroll
        for (int e = 0; e < NEXP; e++) if (e != i0 && logits[e] > v1) { v1 = logits[e]; i1 = e; }
        float e1 = expf(v1 - v0);
        float inv = 1.0f / (1.0f + e1);
        g_expert[warp * 2 + 0] = i0;
        g_expert[warp * 2 + 1] = i1;
        g_weight[warp * 2 + 0] = inv;
        g_weight[warp * 2 + 1] = e1 * inv;
    }
}

// -------- kernel 2: grouping via warp-shuffle scan (2 barriers) --------
#define GT   1024
#define GPER (NPAIR / GT)   // 16
__global__ void __launch_bounds__(GT) group_kernel() {
    __shared__ int s_wtot[NEXP][32];
    __shared__ int s_woff[NEXP][32];
    const int t = threadIdx.x;
    const int warp = t >> 5;
    const int lane = t & 31;

    uint8_t ex[GPER];
    int cnt[NEXP];
#pragma unroll
    for (int e = 0; e < NEXP; e++) cnt[e] = 0;
#pragma unroll
    for (int i = 0; i < GPER; i++) {
        int e = g_expert[t * GPER + i];
        ex[i] = (uint8_t)e;
        cnt[e]++;
    }
    // warp-level inclusive scan per expert
    int incl[NEXP];
#pragma unroll
    for (int e = 0; e < NEXP; e++) {
        int v = cnt[e];
#pragma unroll
        for (int o = 1; o < 32; o <<= 1) {
            int u = __shfl_up_sync(0xffffffffu, v, o);
            if (lane >= o) v += u;
        }
        incl[e] = v;
        if (lane == 31) s_wtot[e][warp] = v;
    }
    __syncthreads();
    if (warp < NEXP) {  // warp w scans expert w's 32 warp totals
        int e = warp;
        int v = s_wtot[e][lane];
        int orig = v;
#pragma unroll
        for (int o = 1; o < 32; o <<= 1) {
            int u = __shfl_up_sync(0xffffffffu, v, o);
            if (lane >= o) v += u;
        }
        s_woff[e][lane] = v - orig;  // exclusive
        if (lane == 31) g_count[e] = v;
    }
    __syncthreads();

    int off[NEXP];
#pragma unroll
    for (int e = 0; e < NEXP; e++) off[e] = s_woff[e][warp] + incl[e] - cnt[e];
#pragma unroll
    for (int i = 0; i < GPER; i++) {
        int e = ex[i];
        g_list[e * NPAIR + off[e]] = t * GPER + i;
        off[e]++;
    }
}

// -------- kernel 3: grouped GEMM, tf32 mma.sync, SW128 smem, 64x64 warp tiles --------
__global__ void __launch_bounds__(256) gemm_kernel() {
    const int e   = blockIdx.z;
    const int cnt = g_count[e];
    const int m0  = blockIdx.y * BM;
    if (m0 >= cnt) return;
    const int n0  = blockIdx.x * BN;

    extern __shared__ __align__(1024) char smem[];
    __shared__ int s_pid[BM];
    __shared__ int s_tok[BM];

    const uint32_t smem_base = smem_u32(smem);
    const int tid = threadIdx.x;
    const int wid = tid >> 5;
    const int lane = tid & 31;
    const int warpM = wid & 1;    // 2 x 64-row bands
    const int warpN = wid >> 1;   // 4 x 64-col bands
    const int gid = lane >> 2;    // 0..7
    const int qid = lane & 3;     // 0..3

    if (tid < BM) {
        int p = (m0 + tid < cnt) ? g_list[e * NPAIR + m0 + tid] : -1;
        s_pid[tid] = p;
        s_tok[tid] = (p >= 0) ? (p >> 1) : 0;
    }
    __syncthreads();

    const float* __restrict__ Wb = g_rW + (size_t)e * DDIM * DDIM;
    const int NKB = DDIM / BK;  // 32

    auto issue_loads = [&](int kb) {
        const uint32_t sbase = smem_base + (uint32_t)(kb % STAGES) * STAGE_BYTES;
        const int kbase = kb * BK;
        // A: 128 rows x 8 chunks of 16B
#pragma unroll
        for (int i = 0; i < 4; i++) {
            int idx = tid + i * 256;
            int r = idx >> 3, c4 = idx & 7;
            const float* g = g_rdelta + (size_t)s_tok[r] * DDIM + kbase + c4 * 4;
            cp_async16(sbase + swz128((uint32_t)(r * 128 + c4 * 16)), g);
        }
        // B: 256 rows x 8 chunks
#pragma unroll
        for (int i = 0; i < 8; i++) {
            int idx = tid + i * 256;
            int r = idx >> 3, c4 = idx & 7;
            const float* g = Wb + (size_t)(n0 + r) * DDIM + kbase + c4 * 4;
            cp_async16(sbase + A_BYTES + swz128((uint32_t)(r * 128 + c4 * 16)), g);
        }
        cp_commit();
    };

    // per-thread swizzled row bases (relative to stage): Q = r*128 + qid*4 | (r&7)*16
    uint32_t qa[8], qb[8];
#pragma unroll
    for (int mt = 0; mt < 4; mt++) {
        int r0 = warpM * 64 + mt * 16 + gid;
        int r1 = r0 + 8;
        qa[mt * 2 + 0] = (uint32_t)(r0 * 128 + qid * 4) | (uint32_t)((r0 & 7) << 4);
        qa[mt * 2 + 1] = (uint32_t)(r1 * 128 + qid * 4) | (uint32_t)((r1 & 7) << 4);
    }
#pragma unroll
    for (int nt = 0; nt < 8; nt++) {
        int n = warpN * 64 + nt * 8 + gid;
        qb[nt] = (uint32_t)(A_BYTES + n * 128 + qid * 4) | (uint32_t)((n & 7) << 4);
    }

    float acc[4][8][4];
#pragma unroll
    for (int mt = 0; mt < 4; mt++)
#pragma unroll
        for (int nt = 0; nt < 8; nt++)
#pragma unroll
            for (int j = 0; j < 4; j++) acc[mt][nt][j] = 0.f;

    issue_loads(0);
    issue_loads(1);

    for (int kb = 0; kb < NKB; kb++) {
        if (kb + 2 < NKB) cp_wait<1>(); else cp_wait<0>();
        __syncthreads();
        if (kb + 2 < NKB) issue_loads(kb + 2);

        const uint32_t sbase = smem_base + (uint32_t)(kb % STAGES) * STAGE_BYTES;
        uint32_t QA[8], QB[8];
#pragma unroll
        for (int i = 0; i < 8; i++) { QA[i] = sbase + qa[i]; QB[i] = sbase + qb[i]; }

#pragma unroll
        for (int ks = 0; ks < 4; ks++) {
            const uint32_t c0 = (uint32_t)((2 * ks + 0) * 16);
            const uint32_t c1 = (uint32_t)((2 * ks + 1) * 16);
            float a[4][4];
#pragma unroll
            for (int mt = 0; mt < 4; mt++) {
                a[mt][0] = lds32(QA[mt * 2 + 0] ^ c0);
                a[mt][1] = lds32(QA[mt * 2 + 1] ^ c0);
                a[mt][2] = lds32(QA[mt * 2 + 0] ^ c1);
                a[mt][3] = lds32(QA[mt * 2 + 1] ^ c1);
            }
            float b[8][2];
#pragma unroll
            for (int nt = 0; nt < 8; nt++) {
                b[nt][0] = lds32(QB[nt] ^ c0);
                b[nt][1] = lds32(QB[nt] ^ c1);
            }
#pragma unroll
            for (int mt = 0; mt < 4; mt++)
#pragma unroll
                for (int nt = 0; nt < 8; nt++)
                    mma_tf32(acc[mt][nt], a[mt], b[nt]);
        }
        __syncthreads();
    }

    // epilogue
#pragma unroll
    for (int mt = 0; mt < 4; mt++) {
        int r0 = warpM * 64 + mt * 16 + gid;
        int r1 = r0 + 8;
        int p0 = s_pid[r0];
        int p1 = s_pid[r1];
#pragma unroll
        for (int nt = 0; nt < 8; nt++) {
            int c = n0 + warpN * 64 + nt * 8 + qid * 2;
            if (p0 >= 0)
                *(float2*)(g_partial + (size_t)p0 * DDIM + c) =
                    make_float2(acc[mt][nt][0], acc[mt][nt][1]);
            if (p1 >= 0)
                *(float2*)(g_partial + (size_t)p1 * DDIM + c) =
                    make_float2(acc[mt][nt][2], acc[mt][nt][3]);
        }
    }
}

// -------- kernel 4: weighted combine with expert bias --------
__global__ void combine_kernel(const float* __restrict__ eb, float* __restrict__ out) {
    int i   = blockIdx.x * blockDim.x + threadIdx.x;
    int tok = i >> 8;
    int c4  = i & 255;
    float w0 = g_weight[tok * 2 + 0], w1 = g_weight[tok * 2 + 1];
    int   e0 = g_expert[tok * 2 + 0], e1 = g_expert[tok * 2 + 1];

    float4 p0 = ((const float4*)(g_partial + (size_t)(tok * 2 + 0) * DDIM))[c4];
    float4 p1 = ((const float4*)(g_partial + (size_t)(tok * 2 + 1) * DDIM))[c4];
    float4 b0 = ((const float4*)(eb + (size_t)e0 * DDIM))[c4];
    float4 b1 = ((const float4*)(eb + (size_t)e1 * DDIM))[c4];

    float4 r;
    r.x = w0 * (p0.x + b0.x) + w1 * (p1.x + b1.x);
    r.y = w0 * (p0.y + b0.y) + w1 * (p1.y + b1.y);
    r.z = w0 * (p0.z + b0.z) + w1 * (p1.z + b1.z);
    r.w = w0 * (p0.w + b0.w) + w1 * (p1.w + b1.w);
    ((float4*)out)[i] = r;
}

// -------- launch --------
extern "C" void kernel_launch(void* const* d_in, const int* in_sizes, int n_in,
                              void* d_out, int out_size) {
    const float* input_feat = (const float*)d_in[0];
    const float* delta      = (const float*)d_in[1];
    const float* gate_W     = (const float*)d_in[2];
    const float* gate_b     = (const float*)d_in[3];
    const float* expert_W   = (const float*)d_in[4];
    const float* expert_b   = (const float*)d_in[5];
    float* out = (float*)d_out;

    cudaFuncSetAttribute(gemm_kernel, cudaFuncAttributeMaxDynamicSharedMemorySize, SMEM_BYTES);

    float* rdelta; cudaGetSymbolAddress((void**)&rdelta, g_rdelta);
    float* rW;     cudaGetSymbolAddress((void**)&rW, g_rW);

    round_kernel<<<(NTOK * DDIM / 4) / 256, 256>>>(delta, rdelta, NTOK * DDIM / 4);
    round_kernel<<<(NEXP * DDIM * DDIM / 4) / 256, 256>>>(expert_W, rW, NEXP * DDIM * DDIM / 4);
    gate_kernel<<<NTOK / 8, 256>>>(input_feat, gate_W, gate_b);
    group_kernel<<<1, GT>>>();
    dim3 grid(DDIM / BN, NPAIR / BM, NEXP);
    gemm_kernel<<<grid, 256, SMEM_BYTES>>>();
    combine_kernel<<<(NTOK * (DDIM / 4)) / 256, 256>>>(expert_b, out);
}